// round 15
// baseline (speedup 1.0000x reference)
#include <cuda_runtime.h>
#include <cstdint>

typedef unsigned long long ull;

__device__ __forceinline__ ull pack2(float a, float b) {
    ull r; asm("mov.b64 %0,{%1,%2};" : "=l"(r) : "f"(a), "f"(b)); return r;
}
__device__ __forceinline__ void fma2(ull& d, ull a, ull b) {
    asm("fma.rn.f32x2 %0,%1,%2,%3;" : "=l"(d) : "l"(a), "l"(b), "l"(d));
}
__device__ __forceinline__ void add2(ull& d, ull a) {
    asm("add.rn.f32x2 %0,%1,%2;" : "=l"(d) : "l"(d), "l"(a));
}
__device__ __forceinline__ float lo2(ull a) { return __uint_as_float((unsigned)a); }
__device__ __forceinline__ float hi2(ull a) { return __uint_as_float((unsigned)(a >> 32)); }

#define CH 8                    // h rows per chunk (56 = 7 * 8)
#define NQUAD 1120              // 16B quads per tile: 4kq * 2n * 10rows * 14
#define XT_BYTES 19200          // bytes per x-tile buffer

struct Smem {
    union {
        float xtile[2][4][2][10][60];   // [buf][kq][n][slot][w(pad60)]  38400 B
        ull   pbuf[2][16][112];         // 2-step reduction partials     28672 B
    } u;
    float M[2][2][CH][4][56];    // [par][n][h][o][w]                    28672 B
    float S[2][2][CH][4][60];    // [par][n][h][o][x] = t4[x-1], 0 pad   30720 B
    ull   w1p[768];              // [k][i][o] packed (w,w)                6144 B
    ull   w2p[192];              // [i][kk][j] packed (w,w)               1536 B
};
#define SMEM_BYTES sizeof(Smem)  // 105472 -> 2 blocks/SM

// Each block processes TWO h-chunks. Phase 2 of chunk 0 is injected, one
// half-row per pipeline stage, into chunk 1's phase-1 cp.async pipeline,
// so stores+fma fill the DRAM-load shadow (blocks are otherwise
// phase-aligned and their memory bursts collide).
__global__ __launch_bounds__(448, 2) void fused_kernel(
    const float* __restrict__ x, const float* __restrict__ w1,
    const float* __restrict__ w2, float* __restrict__ out)
{
    extern __shared__ __align__(16) char smraw[];
    Smem& sm = *reinterpret_cast<Smem*>(smraw);

    const int tid = threadIdx.x;
    const int c0  = blockIdx.x * 2;          // chunks c0, c0+1 ; chunk = l*7+hc

    // ---- fixed smem destinations for the 3 per-thread staging quads ----
    unsigned qdst[3];
#pragma unroll
    for (int i = 0; i < 3; i++) {
        int q  = tid + i * 448;
        int qq = (q < NQUAD) ? q : 0;
        int kq = qq / 280, n = (qq / 140) % 2, s = (qq / 14) % 10, wq = qq % 14;
        qdst[i] = (unsigned)__cvta_generic_to_shared(&sm.u.xtile[0][kq][n][s][wq * 4]);
    }

    const char* xl = nullptr; unsigned qoff[3]; unsigned qszbits = 0;
    auto setup = [&](int c) {                 // per-chunk source descriptors
        int l = c / 7, h0 = (c % 7) * CH;
        xl = reinterpret_cast<const char*>(x) + (size_t)l * 128 * 12544;
        qszbits = 0;
#pragma unroll
        for (int i = 0; i < 3; i++) {
            int q  = tid + i * 448;
            int qq = (q < NQUAD) ? q : 0;
            int kq = qq / 280, n = (qq / 140) % 2, s = (qq / 14) % 10, wq = qq % 14;
            int hv = h0 - 1 + s;              // virtual (rolled) tap row
            int inr = (hv >= 0 && hv < 56);
            int row = (hv == 0) ? 55 : hv - 1;
            qoff[i] = (unsigned)((32 * kq + n) * 12544 + (inr ? row * 224 : 0) + wq * 16);
            qszbits |= (unsigned)inr << i;
        }
    };
    auto issue = [&](int t) {
        unsigned bofs = (unsigned)((t & 1) * XT_BYTES);
        unsigned cofs = (unsigned)(t * 25088);     // +2 channels per tile
#pragma unroll
        for (int i = 0; i < 3; i++) {
            if (i == 2 && tid >= 224) break;
            int sz = (int)((qszbits >> i) & 1u) * 16;
            asm volatile("cp.async.cg.shared.global [%0], [%1], 16, %2;"
                         :: "r"(qdst[i] + bofs), "l"(xl + qoff[i] + cofs), "r"(sz)
                         : "memory");
        }
        asm volatile("cp.async.commit_group;" ::: "memory");
    };

    // ---- phase-1 compute mapping ----
    const int kq  = tid / 112;
    const int rem = tid % 112;
    const int n   = rem / 56;
    const int hp  = (rem / 14) % 4;
    const int w0  = (rem % 14) * 4;

    // ---- phase-2 mapping ----
    const int tx = tid % 14;
    const int ty = tid / 14;
    const int po = ty >> 3;
    const int jb = (ty & 7) * 4;
    const int pw0 = tx * 4;

    ull acc[2][4][2];

    auto p1_zero = [&]() {
#pragma unroll
        for (int h = 0; h < 2; h++)
#pragma unroll
            for (int o = 0; o < 4; o++) { acc[h][o][0] = 0ull; acc[h][o][1] = 0ull; }
    };
    auto p1_stage = [&](int t) {              // consume tile t
        const float* xb = &sm.u.xtile[t & 1][kq][n][0][0];
        ulonglong2 v[4];
#pragma unroll
        for (int r = 0; r < 4; r++)
            v[r] = *reinterpret_cast<const ulonglong2*>(xb + (hp * 2 + r) * 60 + w0);
        const ulonglong2* wk = reinterpret_cast<const ulonglong2*>(&sm.w1p[(kq * 16 + t) * 12]);
#pragma unroll
        for (int p = 0; p < 6; p++) {
            ulonglong2 wv = wk[p];
            const int e0 = 2 * p,     i0 = e0 >> 2, o0 = e0 & 3;
            const int e1 = 2 * p + 1, i1 = e1 >> 2, o1 = e1 & 3;
            fma2(acc[0][o0][0], v[i0].x,     wv.x);
            fma2(acc[0][o0][1], v[i0].y,     wv.x);
            fma2(acc[1][o0][0], v[i0 + 1].x, wv.x);
            fma2(acc[1][o0][1], v[i0 + 1].y, wv.x);
            fma2(acc[0][o1][0], v[i1].x,     wv.y);
            fma2(acc[0][o1][1], v[i1].y,     wv.y);
            fma2(acc[1][o1][0], v[i1 + 1].x, wv.y);
            fma2(acc[1][o1][1], v[i1 + 1].y, wv.y);
        }
    };

    // 2-step k reduction (kq 1,3 publish; 0,2 absorb; 2 republish; 0 finalize)
    auto reduce = [&](int par) {
        if (kq & 1) {
            ull (*dst)[112] = sm.u.pbuf[kq >> 1];
#pragma unroll
            for (int h = 0; h < 2; h++)
#pragma unroll
                for (int o = 0; o < 4; o++)
#pragma unroll
                    for (int wp = 0; wp < 2; wp++)
                        dst[(h * 4 + o) * 2 + wp][rem] = acc[h][o][wp];
        }
        __syncthreads();
        if (!(kq & 1)) {
            ull (*src)[112] = sm.u.pbuf[kq >> 1];
#pragma unroll
            for (int h = 0; h < 2; h++)
#pragma unroll
                for (int o = 0; o < 4; o++)
#pragma unroll
                    for (int wp = 0; wp < 2; wp++)
                        add2(acc[h][o][wp], src[(h * 4 + o) * 2 + wp][rem]);
            if (kq == 2) {
                ull (*dst)[112] = sm.u.pbuf[1];
#pragma unroll
                for (int h = 0; h < 2; h++)
#pragma unroll
                    for (int o = 0; o < 4; o++)
#pragma unroll
                        for (int wp = 0; wp < 2; wp++)
                            dst[(h * 4 + o) * 2 + wp][rem] = acc[h][o][wp];
            }
        }
        __syncthreads();
        if (kq == 0) {
            ull (*src)[112] = sm.u.pbuf[1];
#pragma unroll
            for (int h = 0; h < 2; h++) {
                const int hr = hp * 2 + h;
#pragma unroll
                for (int o = 0; o < 4; o++) {
                    ull s0 = acc[h][o][0], s1 = acc[h][o][1];
                    add2(s0, src[(h * 4 + o) * 2 + 0][rem]);
                    add2(s1, src[(h * 4 + o) * 2 + 1][rem]);
                    *reinterpret_cast<ull*>(&sm.M[par][n][hr][o][w0])     = s0;
                    *reinterpret_cast<ull*>(&sm.M[par][n][hr][o][w0 + 2]) = s1;
                    sm.S[par][n][hr][o][w0 + 1] = lo2(s0);
                    *reinterpret_cast<ull*>(&sm.S[par][n][hr][o][w0 + 2]) = pack2(hi2(s0), lo2(s1));
                    sm.S[par][n][hr][o][w0 + 4] = hi2(s1);
                }
            }
        }
        __syncthreads();
    };

    // phase 2, half a row: 2 of this thread's 4 j values for row h of chunk c
    auto p2_half = [&](int par, int c, int h, int half) {
        const int j0 = jb + half * 2;
        const int l = c / 7, h0 = (c % 7) * CH;
        ull a[2][2];
        a[0][0] = a[0][1] = a[1][0] = a[1][1] = 0ull;
#pragma unroll
        for (int i = 0; i < 2; i++) {
#pragma unroll
            for (int kk = 0; kk < 3; kk++) {
                ull p0, p1;
                if (kk == 1) {
                    p0 = *reinterpret_cast<const ull*>(&sm.M[par][i][h][po][pw0]);
                    p1 = *reinterpret_cast<const ull*>(&sm.M[par][i][h][po][pw0 + 2]);
                } else if (kk == 0) {
                    p0 = *reinterpret_cast<const ull*>(&sm.S[par][i][h][po][pw0]);
                    p1 = *reinterpret_cast<const ull*>(&sm.S[par][i][h][po][pw0 + 2]);
                } else {
                    p0 = *reinterpret_cast<const ull*>(&sm.S[par][i][h][po][pw0 + 2]);
                    p1 = *reinterpret_cast<const ull*>(&sm.S[par][i][h][po][pw0 + 4]);
                }
                ulonglong2 W = *reinterpret_cast<const ulonglong2*>(&sm.w2p[i * 96 + kk * 32 + j0]);
                fma2(a[0][0], p0, W.x); fma2(a[0][1], p1, W.x);
                fma2(a[1][0], p0, W.y); fma2(a[1][1], p1, W.y);
            }
        }
#pragma unroll
        for (int jj = 0; jj < 2; jj++) {
            int cc = (j0 + jj) * 4 + po;
            float4* p = reinterpret_cast<float4*>(
                out + ((size_t)l * 128 + cc) * 3136 + (h0 + h) * 56 + pw0);
            *p = make_float4(lo2(a[jj][0]), hi2(a[jj][0]),
                             lo2(a[jj][1]), hi2(a[jj][1]));
        }
    };

    // ================= block schedule =================
    setup(c0);
    issue(0);

    for (int idx = tid; idx < 768; idx += 448) { float v = w1[idx]; sm.w1p[idx] = pack2(v, v); }
    if (tid < 192) { float v = w2[tid]; sm.w2p[tid] = pack2(v, v); }
    if (tid < 256) {   // zero pad cells of S for both parities: x = 0 and 57
        int par = tid >> 7, r = tid & 127;
        int nn = r >> 6, q = r & 63, hh = q >> 3, oo = (q >> 1) & 3;
        sm.S[par][nn][hh][oo][(r & 1) ? 57 : 0] = 0.f;
    }
    // (stage-0 barrier below publishes these smem writes)

    // ---- P1(c0) ----
    p1_zero();
    for (int t = 0; t < 16; t++) {
        asm volatile("cp.async.wait_group 0;" ::: "memory");
        __syncthreads();
        if (t + 1 < 16) issue(t + 1);
        p1_stage(t);
    }
    __syncthreads();                 // xtile reads done -> pbuf alias safe
    reduce(0);                       // -> M[0], S[0]

    // ---- P1(c1) with P2(c0) injected ----
    setup(c0 + 1);
    issue(0);
    p1_zero();
    for (int t = 0; t < 16; t++) {
        asm volatile("cp.async.wait_group 0;" ::: "memory");
        __syncthreads();
        if (t + 1 < 16) issue(t + 1);
        p2_half(0, c0, t >> 1, t & 1);   // fills the tile-(t+1) load shadow
        p1_stage(t);
    }
    __syncthreads();
    reduce(1);                       // -> M[1], S[1]

    // ---- P2(c1) ----
    for (int h = 0; h < CH; h++) {
        p2_half(1, c0 + 1, h, 0);
        p2_half(1, c0 + 1, h, 1);
    }
}

extern "C" void kernel_launch(void* const* d_in, const int* in_sizes, int n_in,
                              void* d_out, int out_size)
{
    const float* x  = (const float*)d_in[0];
    const float* w1 = (const float*)d_in[1];
    const float* w2 = (const float*)d_in[2];
    float* out = (float*)d_out;

    cudaFuncSetAttribute(fused_kernel, cudaFuncAttributeMaxDynamicSharedMemorySize,
                         (int)SMEM_BYTES);
    fused_kernel<<<dim3(448), 448, SMEM_BYTES>>>(x, w1, w2, out);
}

// round 16
// speedup vs baseline: 1.5294x; 1.5294x over previous
#include <cuda_runtime.h>
#include <cstdint>

typedef unsigned long long ull;

__device__ __forceinline__ ull pack2(float a, float b) {
    ull r; asm("mov.b64 %0,{%1,%2};" : "=l"(r) : "f"(a), "f"(b)); return r;
}
__device__ __forceinline__ void fma2(ull& d, ull a, ull b) {
    asm("fma.rn.f32x2 %0,%1,%2,%3;" : "=l"(d) : "l"(a), "l"(b), "l"(d));
}
__device__ __forceinline__ void add2(ull& d, ull a) {
    asm("add.rn.f32x2 %0,%1,%2;" : "=l"(d) : "l"(d), "l"(a));
}
__device__ __forceinline__ float lo2(ull a) { return __uint_as_float((unsigned)a); }
__device__ __forceinline__ float hi2(ull a) { return __uint_as_float((unsigned)(a >> 32)); }

#define CH 8                    // h rows per block (56 = 7 * 8)
#define XT_BYTES 19200          // bytes per x-tile buffer (both halves)

struct Smem {
    union {
        float xtile[3][2][2][2][10][60];  // [buf][half][kqs][n][slot][w]  57600 B
        ull   pbuf[4][112][17];           // partials, alias               60928 B
    } u;
    float M[2][CH][4][56];       // [n][h][o][w]  = t4 row
    float S[2][CH][4][60];       // [n][h][o][x]  = t4[x-1], 0 pad
    ull   w1p[768];              // [k][i][o] packed (w,w)
    ull   w2p[192];              // [i][kk][j] packed (w,w)
};
#define SMEM_BYTES sizeof(Smem)  // 98304 -> 2 blocks/SM

// R6 pipeline with HALF-BLOCK-scoped synchronization: threads of half h
// (224 = 7 warps) stage and consume only the k-range [32h, 32h+32), so the
// per-stage barrier is bar.sync(1+h, 224). The two halves' pipelines skew
// independently (4 convoys/SM), interleaving DRAM bursts with compute.
__global__ __launch_bounds__(448, 2) void fused_kernel(
    const float* __restrict__ x, const float* __restrict__ w1,
    const float* __restrict__ w2, float* __restrict__ out)
{
    extern __shared__ __align__(16) char smraw[];
    Smem& sm = *reinterpret_cast<Smem*>(smraw);

    const int tid  = threadIdx.x;
    const int half = tid / 224;
    const int htid = tid % 224;
    const int h0   = blockIdx.x * CH;
    const int l    = blockIdx.y;

    // ---- per-thread cp.async descriptors: 3 quads within OWN half ----
    // half-tile = 560 quads (2kqs * 2n * 10rows * 14wq); q = htid + i*224.
    const char* xl = reinterpret_cast<const char*>(x) + (size_t)l * 128 * 12544;
    unsigned qoff[3]; unsigned qdst[3]; unsigned qszbits = 0;
#pragma unroll
    for (int i = 0; i < 3; i++) {
        int q   = htid + i * 224;
        int qq  = (q < 560) ? q : 0;
        int kqs = qq / 280, r = qq % 280;
        int n = r / 140, s = (r / 14) % 10, wq = r % 14;
        int hv  = h0 - 1 + s;                 // virtual (rolled) tap row
        int inr = (hv >= 0 && hv < 56);
        int row = (hv == 0) ? 55 : hv - 1;
        int ch0 = 64 * half + 32 * kqs + n;   // channel at t = 0  (c = 32kq+2t+n)
        qoff[i] = (unsigned)(ch0 * 12544 + (inr ? row * 224 : 0) + wq * 16);
        qdst[i] = (unsigned)__cvta_generic_to_shared(&sm.u.xtile[0][half][kqs][n][s][wq * 4]);
        qszbits |= (unsigned)inr << i;
    }

    auto issue = [&](int t) {
        unsigned bofs = (unsigned)((t % 3) * XT_BYTES);
        unsigned cofs = (unsigned)(t * 25088);     // +2 channels per tile
#pragma unroll
        for (int i = 0; i < 3; i++) {
            if (i == 2 && htid >= 112) break;
            int sz = (int)((qszbits >> i) & 1u) * 16;
            asm volatile("cp.async.cg.shared.global [%0], [%1], 16, %2;"
                         :: "r"(qdst[i] + bofs), "l"(xl + qoff[i] + cofs), "r"(sz)
                         : "memory");
        }
        asm volatile("cp.async.commit_group;" ::: "memory");
    };

    issue(0); issue(1);                  // prologue: 2 tiles in flight per half

    for (int idx = tid; idx < 768; idx += 448) { float v = w1[idx]; sm.w1p[idx] = pack2(v, v); }
    if (tid < 192) { float v = w2[tid]; sm.w2p[tid] = pack2(v, v); }
    if (tid < 128) {   // zero pad cells of S: x = 0 and x = 57
        int n = tid >> 6, rem = tid & 63, h = rem >> 3, o = (rem >> 1) & 3;
        sm.S[n][h][o][(tid & 1) ? 57 : 0] = 0.f;
    }
    __syncthreads();                     // weights/pads cross halves: one block sync

    // ---------------- Phase 1: two independent half-pipelines ----------------
    const int kq  = tid / 112;           // = 2*half + kqs
    const int kqs = kq & 1;
    const int rem = tid % 112;
    const int n   = rem / 56;
    const int hp  = (rem / 14) % 4;
    const int wq  = rem % 14;
    const int w0  = wq * 4;

    ull acc[2][4][2];
#pragma unroll
    for (int h = 0; h < 2; h++)
#pragma unroll
        for (int o = 0; o < 4; o++) { acc[h][o][0] = 0ull; acc[h][o][1] = 0ull; }

    for (int t = 0; t < 16; t++) {
        if (t < 15) asm volatile("cp.async.wait_group 1;" ::: "memory");
        else        asm volatile("cp.async.wait_group 0;" ::: "memory");
        asm volatile("bar.sync %0, 224;" :: "r"(1 + half) : "memory");
                                         // tile t visible to this half; buf(t+2)%3 free
        if (t + 2 < 16) issue(t + 2);    // overwrites buffer last read at t-1

        const float* xb = &sm.u.xtile[t % 3][half][kqs][n][0][0];
        ulonglong2 v[4];
#pragma unroll
        for (int r = 0; r < 4; r++)
            v[r] = *reinterpret_cast<const ulonglong2*>(xb + (hp * 2 + r) * 60 + w0);

        const ulonglong2* wk = reinterpret_cast<const ulonglong2*>(&sm.w1p[(kq * 16 + t) * 12]);
#pragma unroll
        for (int p = 0; p < 6; p++) {
            ulonglong2 wv = wk[p];
            const int e0 = 2 * p,     i0 = e0 >> 2, o0 = e0 & 3;
            const int e1 = 2 * p + 1, i1 = e1 >> 2, o1 = e1 & 3;
            fma2(acc[0][o0][0], v[i0].x,     wv.x);
            fma2(acc[0][o0][1], v[i0].y,     wv.x);
            fma2(acc[1][o0][0], v[i0 + 1].x, wv.x);
            fma2(acc[1][o0][1], v[i0 + 1].y, wv.x);
            fma2(acc[0][o1][0], v[i1].x,     wv.y);
            fma2(acc[0][o1][1], v[i1].y,     wv.y);
            fma2(acc[1][o1][0], v[i1 + 1].x, wv.y);
            fma2(acc[1][o1][1], v[i1 + 1].y, wv.y);
        }
    }
    __syncthreads();                     // both halves done -> pbuf alias safe

    // publish partials
    {
        ull* dst = &sm.u.pbuf[kq][rem][0];
#pragma unroll
        for (int h = 0; h < 2; h++)
#pragma unroll
            for (int o = 0; o < 4; o++)
#pragma unroll
                for (int wp = 0; wp < 2; wp++)
                    dst[(h * 4 + o) * 2 + wp] = acc[h][o][wp];
    }
    __syncthreads();

    // parallel reduction + t4 smem write: thread = (item, o)
    {
        const int it = tid % 112;
        const int o2 = tid / 112;
        ull s[2][2];
#pragma unroll
        for (int h = 0; h < 2; h++)
#pragma unroll
            for (int wp = 0; wp < 2; wp++)
                s[h][wp] = sm.u.pbuf[0][it][(h * 4 + o2) * 2 + wp];
#pragma unroll
        for (int q = 1; q < 4; q++)
#pragma unroll
            for (int h = 0; h < 2; h++)
#pragma unroll
                for (int wp = 0; wp < 2; wp++)
                    add2(s[h][wp], sm.u.pbuf[q][it][(h * 4 + o2) * 2 + wp]);

        const int rn  = it / 56;
        const int rhp = (it / 14) % 4;
        const int rw0 = (it % 14) * 4;
#pragma unroll
        for (int h = 0; h < 2; h++) {
            const int hr = rhp * 2 + h;
            *reinterpret_cast<ull*>(&sm.M[rn][hr][o2][rw0])     = s[h][0];
            *reinterpret_cast<ull*>(&sm.M[rn][hr][o2][rw0 + 2]) = s[h][1];
            sm.S[rn][hr][o2][rw0 + 1] = lo2(s[h][0]);
            *reinterpret_cast<ull*>(&sm.S[rn][hr][o2][rw0 + 2]) = pack2(hi2(s[h][0]), lo2(s[h][1]));
            sm.S[rn][hr][o2][rw0 + 4] = hi2(s[h][1]);
        }
    }
    __syncthreads();

    // ---------------- Phase 2 ----------------
    {
        const int tx = tid % 14;
        const int ty = tid / 14;
        const int o  = ty >> 3;
        const int j0 = (ty & 7) * 4;
        const int pw0 = tx * 4;

        for (int h = 0; h < CH; h++) {
            ull acc2[4][2];
#pragma unroll
            for (int jj = 0; jj < 4; jj++) { acc2[jj][0] = 0ull; acc2[jj][1] = 0ull; }

#pragma unroll
            for (int i = 0; i < 2; i++) {
#pragma unroll
                for (int kk = 0; kk < 3; kk++) {
                    ull p0, p1;
                    if (kk == 1) {
                        p0 = *reinterpret_cast<const ull*>(&sm.M[i][h][o][pw0]);
                        p1 = *reinterpret_cast<const ull*>(&sm.M[i][h][o][pw0 + 2]);
                    } else if (kk == 0) {
                        p0 = *reinterpret_cast<const ull*>(&sm.S[i][h][o][pw0]);
                        p1 = *reinterpret_cast<const ull*>(&sm.S[i][h][o][pw0 + 2]);
                    } else {
                        p0 = *reinterpret_cast<const ull*>(&sm.S[i][h][o][pw0 + 2]);
                        p1 = *reinterpret_cast<const ull*>(&sm.S[i][h][o][pw0 + 4]);
                    }
                    ulonglong2 Wa = *reinterpret_cast<const ulonglong2*>(&sm.w2p[i * 96 + kk * 32 + j0]);
                    ulonglong2 Wb = *reinterpret_cast<const ulonglong2*>(&sm.w2p[i * 96 + kk * 32 + j0 + 2]);
                    fma2(acc2[0][0], p0, Wa.x); fma2(acc2[0][1], p1, Wa.x);
                    fma2(acc2[1][0], p0, Wa.y); fma2(acc2[1][1], p1, Wa.y);
                    fma2(acc2[2][0], p0, Wb.x); fma2(acc2[2][1], p1, Wb.x);
                    fma2(acc2[3][0], p0, Wb.y); fma2(acc2[3][1], p1, Wb.y);
                }
            }

#pragma unroll
            for (int jj = 0; jj < 4; jj++) {
                int cc = (j0 + jj) * 4 + o;
                float4* p = reinterpret_cast<float4*>(
                    out + ((size_t)l * 128 + cc) * 3136 + (h0 + h) * 56 + pw0);
                *p = make_float4(lo2(acc2[jj][0]), hi2(acc2[jj][0]),
                                 lo2(acc2[jj][1]), hi2(acc2[jj][1]));
            }
        }
    }
}

extern "C" void kernel_launch(void* const* d_in, const int* in_sizes, int n_in,
                              void* d_out, int out_size)
{
    const float* x  = (const float*)d_in[0];
    const float* w1 = (const float*)d_in[1];
    const float* w2 = (const float*)d_in[2];
    float* out = (float*)d_out;

    cudaFuncSetAttribute(fused_kernel, cudaFuncAttributeMaxDynamicSharedMemorySize,
                         (int)SMEM_BYTES);
    fused_kernel<<<dim3(7, 128), 448, SMEM_BYTES>>>(x, w1, w2, out);
}